// round 11
// baseline (speedup 1.0000x reference)
#include <cuda_runtime.h>
#include <cstdint>

// Problem constants
#define NB   256
#define SEQ  720
#define PRED 720
#define RNK  16
#define CTXD 128
#define HIDD 64
#define ODIM (RNK*(SEQ+PRED))   // 23040
#define BOFF (RNK*PRED)         // 11520, B_delta at h[b][11520 + r*720 + s]
#define YSZ  (NB*PRED)          // 184320

// Scratch (device globals: allocation-free)
__device__ __align__(128) float g_hidden[NB*HIDD];
__device__ __align__(128) float g_h[(size_t)NB*ODIM];   // hyper-MLP output, 23.6 MB
__device__ __align__(128) float g_t[NB*RNK];

// ---------------- packed f32x2 + async-copy helpers ----------------
__device__ __forceinline__ unsigned long long ffma2(unsigned long long a,
                                                    unsigned long long b,
                                                    unsigned long long c) {
    unsigned long long d;
    asm("fma.rn.f32x2 %0, %1, %2, %3;" : "=l"(d) : "l"(a), "l"(b), "l"(c));
    return d;
}
__device__ __forceinline__ unsigned long long dup2(float a) {
    unsigned long long d;
    asm("mov.b64 %0, {%1, %1};" : "=l"(d) : "f"(a));
    return d;
}
__device__ __forceinline__ float4 u2f4(unsigned long long a, unsigned long long b) {
    union { ulonglong2 u; float4 f; } c; c.u.x = a; c.u.y = b; return c.f;
}
__device__ __forceinline__ void unpack2(unsigned long long v, float& lo, float& hi) {
    asm("mov.b64 {%0, %1}, %2;" : "=f"(lo), "=f"(hi) : "l"(v));
}
__device__ __forceinline__ void cp16(void* smem_dst, const void* gmem_src) {
    unsigned s = (unsigned)__cvta_generic_to_shared(smem_dst);
    asm volatile("cp.async.cg.shared.global [%0], [%1], 16;" :: "r"(s), "l"(gmem_src));
}
#define CP_COMMIT() asm volatile("cp.async.commit_group;")
#define CP_WAIT0()  asm volatile("cp.async.wait_group 0;")

// ---------------- kernel 1a: hidden = relu(ctx @ W1^T + b1) ----------------
__global__ void hidden_kernel(const float* __restrict__ ctx,
                              const float* __restrict__ W1,
                              const float* __restrict__ b1) {
    __shared__ float sc[CTXD];
    int b = blockIdx.x;
    int t = threadIdx.x;               // 128 threads
    sc[t] = ctx[b*CTXD + t];
    __syncthreads();
    if (t < HIDD) {
        float s = b1[t];
        const float* w = W1 + t*CTXD;
        #pragma unroll 16
        for (int k = 0; k < CTXD; ++k) s += w[k]*sc[k];
        g_hidden[b*HIDD + t] = fmaxf(s, 0.f);
    }
}

// ---------------- kernel 1b: h = hidden @ W2^T + b2  (M=23040,N=256,K=64) ----
__global__ void __launch_bounds__(256) mlp2_kernel(const float* __restrict__ W2,
                                                   const float* __restrict__ b2) {
    __shared__ float sW2T[64*68];   // [k][o_local]
    __shared__ float sHT [64*68];   // [k][b_local]
    const int tx = threadIdx.x, ty = threadIdx.y;
    const int tid = ty*16 + tx;
    const int o0 = blockIdx.x*64, b0 = blockIdx.y*64;

    for (int idx = tid; idx < 4096; idx += 256) {
        int i = idx >> 6, k = idx & 63;
        sW2T[k*68 + i] = W2[(size_t)(o0+i)*HIDD + k];
        sHT [k*68 + i] = g_hidden[(b0+i)*HIDD + k];
    }
    __syncthreads();

    unsigned long long acc[4][2];
    #pragma unroll
    for (int j = 0; j < 4; ++j) { acc[j][0] = 0ull; acc[j][1] = 0ull; }

    #pragma unroll 16
    for (int k = 0; k < 64; ++k) {
        float4 hb = *reinterpret_cast<const float4*>(&sHT[k*68 + tx*4]);
        ulonglong2 w = *reinterpret_cast<const ulonglong2*>(&sW2T[k*68 + ty*4]);
        const float hv[4] = {hb.x, hb.y, hb.z, hb.w};
        #pragma unroll
        for (int j = 0; j < 4; ++j) {
            unsigned long long ap = dup2(hv[j]);
            acc[j][0] = ffma2(ap, w.x, acc[j][0]);
            acc[j][1] = ffma2(ap, w.y, acc[j][1]);
        }
    }
    float4 bias = *reinterpret_cast<const float4*>(&b2[o0 + ty*4]);
    #pragma unroll
    for (int j = 0; j < 4; ++j) {
        float4 v = u2f4(acc[j][0], acc[j][1]);
        v.x += bias.x; v.y += bias.y; v.z += bias.z; v.w += bias.w;
        *reinterpret_cast<float4*>(&g_h[(size_t)(b0 + tx*4 + j)*ODIM + o0 + ty*4]) = v;
    }
}

// ---------------- kernel 2: t[b][r] = B_delta[b,r,:] @ x[b,:] ----------------
__global__ void t_kernel(const float* __restrict__ x) {
    int b = blockIdx.x;
    int tid = threadIdx.x;            // 256 threads
    int r = tid >> 4, l = tid & 15;
    const float* bd = g_h + (size_t)b*ODIM + BOFF + r*SEQ;
    const float* xb = x + b*SEQ;
    float s = 0.f;
    for (int i = l; i < SEQ; i += 16) s += bd[i]*xb[i];
    #pragma unroll
    for (int off = 8; off; off >>= 1) s += __shfl_down_sync(0xffffffffu, s, off, 16);
    if (l == 0) g_t[b*RNK + r] = s;
}

// ---------------- kernel 3a: y init = A[b,p,:]·t[b,:] ------------------------
__global__ void yinit_kernel(float* __restrict__ y) {
    int idx = blockIdx.x*256 + threadIdx.x;   // grid 720
    int b = idx / PRED, p = idx - b*PRED;
    const float* a = g_h + (size_t)b*ODIM + p*RNK;
    const float* t = g_t + b*RNK;
    float s = 0.f;
    #pragma unroll
    for (int r = 0; r < RNK; ++r) s += a[r]*t[r];
    y[idx] = s;
}

// ---------------- kernel 3b: y += W@x, split-K with atomics ------------------
#define YP  16
#define YB  64
#define YKP 90            // k-pairs per chunk (180 k)
#define YXST 65           // sX2 row stride in float2
#define Y_SMEM (YKP*YXST*8 + YP*YKP*8)    // 58320 bytes

__global__ void __launch_bounds__(256) ysplit_kernel(const float* __restrict__ W,
                                                     const float* __restrict__ x,
                                                     float* __restrict__ y) {
    extern __shared__ float ysm[];
    float2* sX2 = reinterpret_cast<float2*>(ysm);            // [kk][b] padded
    float2* sW2 = sX2 + YKP*YXST;                            // [p][kk]

    const int tx = threadIdx.x, ty = threadIdx.y;            // (64,4)
    const int tid = ty*64 + tx;
    const int p0 = blockIdx.x*YP, b0 = blockIdx.y*YB;
    const int k0 = blockIdx.z*YKP*2;

    for (int idx = tid; idx < YB*YKP; idx += 256) {
        int b = idx / YKP, kk = idx - (idx/YKP)*YKP;
        sX2[kk*YXST + b] =
            *reinterpret_cast<const float2*>(&x[(size_t)(b0+b)*SEQ + k0 + kk*2]);
    }
    for (int idx = tid; idx < YP*YKP; idx += 256) {
        int p = idx / YKP, kk = idx - (idx/YKP)*YKP;
        sW2[p*YKP + kk] =
            *reinterpret_cast<const float2*>(&W[(size_t)(p0+p)*SEQ + k0 + kk*2]);
    }
    __syncthreads();

    unsigned long long acc[4] = {0ull, 0ull, 0ull, 0ull};
    #pragma unroll 10
    for (int kk = 0; kk < YKP; ++kk) {
        unsigned long long xv =
            *reinterpret_cast<const unsigned long long*>(&sX2[kk*YXST + tx]);
        #pragma unroll
        for (int i = 0; i < 4; ++i) {
            unsigned long long wv =
                *reinterpret_cast<const unsigned long long*>(&sW2[(ty*4+i)*YKP + kk]);
            acc[i] = ffma2(wv, xv, acc[i]);
        }
    }
    const int b = b0 + tx;
    #pragma unroll
    for (int i = 0; i < 4; ++i) {
        float lo, hi; unpack2(acc[i], lo, hi);
        atomicAdd(&y[(size_t)b*PRED + p0 + ty*4 + i], lo + hi);
    }
}

// ---------------- kernel 4: W_eff = W + A_delta @ B_delta --------------------
// TP=24: smem 57.3KB -> 3 blocks/SM (24 warps) AND double-buffered cp.async
// pipeline (1 barrier/batch). Proven R8 inner form (plain A + dup2).
// Per thread: 6 rows (ty*6..ty*6+5) x 8 cols; acc 12 u64 -> ~60 regs.
#define TP 24
#define TS 240
#define SB_F (16*TS)                       // 3840 floats per B buffer
#define SA_ST 28                           // A row stride in floats (24 + pad)
#define SA_F (RNK*SA_ST)                   // 448 floats per A buffer
#define BCH 64                             // batches per block (z=4)
#define WEFF_SMEM ((TP*TS + 2*SB_F + 2*SA_F)*4)   // 57472 bytes

__global__ void __launch_bounds__(256, 3) weff_kernel(const float* __restrict__ W,
                                                      float* __restrict__ weff) {
    extern __shared__ float smem[];
    float* sW = smem;                                 // [TP][TS]
    float* sB = smem + TP*TS;                         // [2][16][TS]
    float* sA = smem + TP*TS + 2*SB_F;                // [2][16][SA_ST] plain

    const int tx = threadIdx.x, ty = threadIdx.y;     // blockDim (64,4)
    const int tid = ty*64 + tx;
    const int p0 = blockIdx.x * TP;
    const int s0 = blockIdx.y * TS;
    const int b_beg = blockIdx.z * BCH;
    const int b_end = min(NB, b_beg + BCH);
    const bool active = (tx < TS/4);
    const int scol = tx*4;
    const int prow = ty*6;                            // 6 contiguous rows

    // W tile -> SMEM, once per block
    for (int idx = tid; idx < TP*TS/4; idx += 256) {
        int row = idx / (TS/4), col = idx % (TS/4);
        float4 v = *reinterpret_cast<const float4*>(&W[(size_t)(p0+row)*SEQ + s0 + col*4]);
        *reinterpret_cast<float4*>(&sW[row*TS + col*4]) = v;
    }

    // prologue: batch b_beg into buffer 0
    {
        const float* hb0 = g_h + (size_t)b_beg*ODIM;
        for (int idx = tid; idx < 16*TS/4; idx += 256) {
            int r = idx / (TS/4), col = idx % (TS/4);
            cp16(&sB[r*TS + col*4], &hb0[BOFF + r*SEQ + s0 + col*4]);
        }
        CP_COMMIT();
        for (int idx = tid; idx < TP*RNK; idx += 256) {
            int p = idx >> 4, r = idx & 15;
            sA[r*SA_ST + p] = hb0[p0*RNK + idx];
        }
        CP_WAIT0();
    }
    __syncthreads();

    for (int b = b_beg; b < b_end; ++b) {
        const int cur = (b - b_beg) & 1;
        const int nxt = cur ^ 1;
        const bool pf = (b + 1 < b_end);
        float apre[2];

        // issue prefetch for b+1 (cp.async B tile; A via LDG into regs)
        if (pf) {
            const float* hbn = g_h + (size_t)(b+1)*ODIM;
            for (int idx = tid; idx < 16*TS/4; idx += 256) {
                int r = idx / (TS/4), col = idx % (TS/4);
                cp16(&sB[nxt*SB_F + r*TS + col*4], &hbn[BOFF + r*SEQ + s0 + col*4]);
            }
            CP_COMMIT();
            #pragma unroll
            for (int k = 0; k < 2; ++k) {
                int idx = tid + k*256;
                apre[k] = (idx < TP*RNK) ? hbn[p0*RNK + idx] : 0.f;
            }
        }

        if (active) {
            const float* sBc = sB + cur*SB_F;
            const float* sAc = sA + cur*SA_F;

            unsigned long long acc[6][2];
            #pragma unroll
            for (int i = 0; i < 6; ++i) {
                ulonglong2 w = *reinterpret_cast<const ulonglong2*>(
                    &sW[(prow+i)*TS + scol]);
                acc[i][0] = w.x; acc[i][1] = w.y;
            }

            #pragma unroll
            for (int r = 0; r < RNK; ++r) {
                ulonglong2 bv = *reinterpret_cast<const ulonglong2*>(&sBc[r*TS + scol]);
                // 3 broadcast LDS.64 cover the 6 A values (prow even -> 8B aligned)
                const float2* ap2 = reinterpret_cast<const float2*>(&sAc[r*SA_ST + prow]);
                float2 a01 = ap2[0], a23 = ap2[1], a45 = ap2[2];
                unsigned long long d0 = dup2(a01.x), d1 = dup2(a01.y);
                unsigned long long d2 = dup2(a23.x), d3 = dup2(a23.y);
                unsigned long long d4 = dup2(a45.x), d5 = dup2(a45.y);
                acc[0][0] = ffma2(d0, bv.x, acc[0][0]);
                acc[0][1] = ffma2(d0, bv.y, acc[0][1]);
                acc[1][0] = ffma2(d1, bv.x, acc[1][0]);
                acc[1][1] = ffma2(d1, bv.y, acc[1][1]);
                acc[2][0] = ffma2(d2, bv.x, acc[2][0]);
                acc[2][1] = ffma2(d2, bv.y, acc[2][1]);
                acc[3][0] = ffma2(d3, bv.x, acc[3][0]);
                acc[3][1] = ffma2(d3, bv.y, acc[3][1]);
                acc[4][0] = ffma2(d4, bv.x, acc[4][0]);
                acc[4][1] = ffma2(d4, bv.y, acc[4][1]);
                acc[5][0] = ffma2(d5, bv.x, acc[5][0]);
                acc[5][1] = ffma2(d5, bv.y, acc[5][1]);
            }

            #pragma unroll
            for (int i = 0; i < 6; ++i) {
                size_t off = ((size_t)b*PRED + (p0 + prow + i))*SEQ + s0 + scol;
                __stcs(reinterpret_cast<float4*>(&weff[off]),
                       u2f4(acc[i][0], acc[i][1]));
            }
        }

        if (pf) {
            #pragma unroll
            for (int k = 0; k < 2; ++k) {
                int idx = tid + k*256;
                if (idx < TP*RNK) {
                    int p = idx >> 4, r = idx & 15;
                    sA[nxt*SA_F + r*SA_ST + p] = apre[k];
                }
            }
            CP_WAIT0();
        }
        __syncthreads();
    }
}

// ---------------- launch ----------------
extern "C" void kernel_launch(void* const* d_in, const int* in_sizes, int n_in,
                              void* d_out, int out_size) {
    const float* x   = (const float*)d_in[0];  // (256,720,1)
    const float* ctx = (const float*)d_in[1];  // (256,128)
    const float* W   = (const float*)d_in[2];  // (720,720)
    const float* W1  = (const float*)d_in[3];  // (64,128)
    const float* b1  = (const float*)d_in[4];  // (64,)
    const float* W2  = (const float*)d_in[5];  // (23040,64)
    const float* b2  = (const float*)d_in[6];  // (23040,)
    float* out  = (float*)d_out;
    float* y    = out;            // first YSZ elements
    float* weff = out + YSZ;      // then W_eff

    hidden_kernel<<<NB, 128>>>(ctx, W1, b1);
    mlp2_kernel<<<dim3(ODIM/64, NB/64), dim3(16,16)>>>(W2, b2);
    t_kernel<<<NB, 256>>>(x);
    yinit_kernel<<<YSZ/256, 256>>>(y);

    cudaFuncSetAttribute(ysplit_kernel, cudaFuncAttributeMaxDynamicSharedMemorySize, Y_SMEM);
    ysplit_kernel<<<dim3(PRED/YP, NB/YB, 4), dim3(64,4), Y_SMEM>>>(W, x, y);

    cudaFuncSetAttribute(weff_kernel, cudaFuncAttributeMaxDynamicSharedMemorySize, WEFF_SMEM);
    weff_kernel<<<dim3(PRED/TP, SEQ/TS, 4), dim3(64,4), WEFF_SMEM>>>(W, weff);
}

// round 12
// speedup vs baseline: 1.7824x; 1.7824x over previous
#include <cuda_runtime.h>
#include <cstdint>

// Problem constants
#define NB   256
#define SEQ  720
#define PRED 720
#define RNK  16
#define CTXD 128
#define HIDD 64
#define ODIM (RNK*(SEQ+PRED))   // 23040
#define BOFF (RNK*PRED)         // 11520, B_delta at h[b][11520 + r*720 + s]
#define YSZ  (NB*PRED)          // 184320

// Scratch (device globals: allocation-free)
__device__ __align__(128) float g_hidden[NB*HIDD];
__device__ __align__(128) float g_h[(size_t)NB*ODIM];   // hyper-MLP output, 23.6 MB
__device__ __align__(128) float g_t[NB*RNK];

// ---------------- packed f32x2 + async-copy helpers ----------------
__device__ __forceinline__ unsigned long long ffma2(unsigned long long a,
                                                    unsigned long long b,
                                                    unsigned long long c) {
    unsigned long long d;
    asm("fma.rn.f32x2 %0, %1, %2, %3;" : "=l"(d) : "l"(a), "l"(b), "l"(c));
    return d;
}
__device__ __forceinline__ unsigned long long dup2(float a) {
    unsigned long long d;
    asm("mov.b64 %0, {%1, %1};" : "=l"(d) : "f"(a));
    return d;
}
__device__ __forceinline__ float4 u2f4(unsigned long long a, unsigned long long b) {
    union { ulonglong2 u; float4 f; } c; c.u.x = a; c.u.y = b; return c.f;
}
__device__ __forceinline__ void unpack2(unsigned long long v, float& lo, float& hi) {
    asm("mov.b64 {%0, %1}, %2;" : "=f"(lo), "=f"(hi) : "l"(v));
}
__device__ __forceinline__ void cp16(void* smem_dst, const void* gmem_src) {
    unsigned s = (unsigned)__cvta_generic_to_shared(smem_dst);
    asm volatile("cp.async.cg.shared.global [%0], [%1], 16;" :: "r"(s), "l"(gmem_src));
}
#define CP_COMMIT() asm volatile("cp.async.commit_group;")
#define CP_WAIT0()  asm volatile("cp.async.wait_group 0;")

// ---------------- kernel 1a: hidden = relu(ctx @ W1^T + b1) ----------------
__global__ void hidden_kernel(const float* __restrict__ ctx,
                              const float* __restrict__ W1,
                              const float* __restrict__ b1) {
    __shared__ float sc[CTXD];
    int b = blockIdx.x;
    int t = threadIdx.x;               // 128 threads
    sc[t] = ctx[b*CTXD + t];
    __syncthreads();
    if (t < HIDD) {
        float s = b1[t];
        const float* w = W1 + t*CTXD;
        #pragma unroll 16
        for (int k = 0; k < CTXD; ++k) s += w[k]*sc[k];
        g_hidden[b*HIDD + t] = fmaxf(s, 0.f);
    }
}

// ---------------- kernel 1b: h = hidden @ W2^T + b2  (M=23040,N=256,K=64) ----
__global__ void __launch_bounds__(256) mlp2_kernel(const float* __restrict__ W2,
                                                   const float* __restrict__ b2) {
    __shared__ float sW2T[64*68];   // [k][o_local]
    __shared__ float sHT [64*68];   // [k][b_local]
    const int tx = threadIdx.x, ty = threadIdx.y;
    const int tid = ty*16 + tx;
    const int o0 = blockIdx.x*64, b0 = blockIdx.y*64;

    for (int idx = tid; idx < 4096; idx += 256) {
        int i = idx >> 6, k = idx & 63;
        sW2T[k*68 + i] = W2[(size_t)(o0+i)*HIDD + k];
        sHT [k*68 + i] = g_hidden[(b0+i)*HIDD + k];
    }
    __syncthreads();

    unsigned long long acc[4][2];
    #pragma unroll
    for (int j = 0; j < 4; ++j) { acc[j][0] = 0ull; acc[j][1] = 0ull; }

    #pragma unroll 16
    for (int k = 0; k < 64; ++k) {
        float4 hb = *reinterpret_cast<const float4*>(&sHT[k*68 + tx*4]);
        ulonglong2 w = *reinterpret_cast<const ulonglong2*>(&sW2T[k*68 + ty*4]);
        const float hv[4] = {hb.x, hb.y, hb.z, hb.w};
        #pragma unroll
        for (int j = 0; j < 4; ++j) {
            unsigned long long ap = dup2(hv[j]);
            acc[j][0] = ffma2(ap, w.x, acc[j][0]);
            acc[j][1] = ffma2(ap, w.y, acc[j][1]);
        }
    }
    float4 bias = *reinterpret_cast<const float4*>(&b2[o0 + ty*4]);
    #pragma unroll
    for (int j = 0; j < 4; ++j) {
        float4 v = u2f4(acc[j][0], acc[j][1]);
        v.x += bias.x; v.y += bias.y; v.z += bias.z; v.w += bias.w;
        *reinterpret_cast<float4*>(&g_h[(size_t)(b0 + tx*4 + j)*ODIM + o0 + ty*4]) = v;
    }
}

// ---------------- kernel 2: t[b][r] = B_delta[b,r,:] @ x[b,:] ----------------
__global__ void t_kernel(const float* __restrict__ x) {
    int b = blockIdx.x;
    int tid = threadIdx.x;            // 256 threads
    int r = tid >> 4, l = tid & 15;
    const float* bd = g_h + (size_t)b*ODIM + BOFF + r*SEQ;
    const float* xb = x + b*SEQ;
    float s = 0.f;
    for (int i = l; i < SEQ; i += 16) s += bd[i]*xb[i];
    #pragma unroll
    for (int off = 8; off; off >>= 1) s += __shfl_down_sync(0xffffffffu, s, off, 16);
    if (l == 0) g_t[b*RNK + r] = s;
}

// ---------------- kernel 3a: y init = A[b,p,:]·t[b,:] ------------------------
__global__ void yinit_kernel(float* __restrict__ y) {
    int idx = blockIdx.x*256 + threadIdx.x;   // grid 720
    int b = idx / PRED, p = idx - b*PRED;
    const float* a = g_h + (size_t)b*ODIM + p*RNK;
    const float* t = g_t + b*RNK;
    float s = 0.f;
    #pragma unroll
    for (int r = 0; r < RNK; ++r) s += a[r]*t[r];
    y[idx] = s;
}

// ---------------- kernel 3b: y += W@x, split-K with atomics ------------------
#define YP  16
#define YB  64
#define YKP 90            // k-pairs per chunk (180 k)
#define YXST 65           // sX2 row stride in float2
#define Y_SMEM (YKP*YXST*8 + YP*YKP*8)    // 58320 bytes

__global__ void __launch_bounds__(256) ysplit_kernel(const float* __restrict__ W,
                                                     const float* __restrict__ x,
                                                     float* __restrict__ y) {
    extern __shared__ float ysm[];
    float2* sX2 = reinterpret_cast<float2*>(ysm);            // [kk][b] padded
    float2* sW2 = sX2 + YKP*YXST;                            // [p][kk]

    const int tx = threadIdx.x, ty = threadIdx.y;            // (64,4)
    const int tid = ty*64 + tx;
    const int p0 = blockIdx.x*YP, b0 = blockIdx.y*YB;
    const int k0 = blockIdx.z*YKP*2;

    for (int idx = tid; idx < YB*YKP; idx += 256) {
        int b = idx / YKP, kk = idx - (idx/YKP)*YKP;
        sX2[kk*YXST + b] =
            *reinterpret_cast<const float2*>(&x[(size_t)(b0+b)*SEQ + k0 + kk*2]);
    }
    for (int idx = tid; idx < YP*YKP; idx += 256) {
        int p = idx / YKP, kk = idx - (idx/YKP)*YKP;
        sW2[p*YKP + kk] =
            *reinterpret_cast<const float2*>(&W[(size_t)(p0+p)*SEQ + k0 + kk*2]);
    }
    __syncthreads();

    unsigned long long acc[4] = {0ull, 0ull, 0ull, 0ull};
    #pragma unroll 10
    for (int kk = 0; kk < YKP; ++kk) {
        unsigned long long xv =
            *reinterpret_cast<const unsigned long long*>(&sX2[kk*YXST + tx]);
        #pragma unroll
        for (int i = 0; i < 4; ++i) {
            unsigned long long wv =
                *reinterpret_cast<const unsigned long long*>(&sW2[(ty*4+i)*YKP + kk]);
            acc[i] = ffma2(wv, xv, acc[i]);
        }
    }
    const int b = b0 + tx;
    #pragma unroll
    for (int i = 0; i < 4; ++i) {
        float lo, hi; unpack2(acc[i], lo, hi);
        atomicAdd(&y[(size_t)b*PRED + p0 + ty*4 + i], lo + hi);
    }
}

// ---------------- kernel 4: W_eff = W + A_delta @ B_delta --------------------
// TP=40, TS=240: smem 74.75KB -> 3 blocks/SM (24 warps) AND double-buffered
// pipeline, with compute/block-batch at 0.83x of the proven TP=48 config
// (load:compute ratio nearly preserved -- the R11 failure mode avoided).
// 10 rows/thread (prow=ty*10, even): acc 20 u64 + temps ~= 75 regs < 85 cap.
#define TP 40
#define TS 240
#define SB_F (16*TS)                       // 3840 floats per B buffer
#define SA_ST 44                           // A row stride in floats (40 + pad)
#define SA_F (RNK*SA_ST)                   // 704 floats per A buffer
#define BCH 32                             // batches per block (z=8)
#define WEFF_SMEM ((TP*TS + 2*SB_F + 2*SA_F)*4)   // 74752 bytes

__global__ void __launch_bounds__(256, 3) weff_kernel(const float* __restrict__ W,
                                                      float* __restrict__ weff) {
    extern __shared__ float smem[];
    float* sW = smem;                                 // [TP][TS]
    float* sB = smem + TP*TS;                         // [2][16][TS]
    float* sA = smem + TP*TS + 2*SB_F;                // [2][16][SA_ST] plain

    const int tx = threadIdx.x, ty = threadIdx.y;     // blockDim (64,4)
    const int tid = ty*64 + tx;
    const int p0 = blockIdx.x * TP;
    const int s0 = blockIdx.y * TS;
    const int b_beg = blockIdx.z * BCH;
    const int b_end = min(NB, b_beg + BCH);
    const bool active = (tx < TS/4);
    const int scol = tx*4;
    const int prow = ty*10;                           // 10 contiguous rows, even

    // W tile -> SMEM, once per block
    for (int idx = tid; idx < TP*TS/4; idx += 256) {
        int row = idx / (TS/4), col = idx % (TS/4);
        float4 v = *reinterpret_cast<const float4*>(&W[(size_t)(p0+row)*SEQ + s0 + col*4]);
        *reinterpret_cast<float4*>(&sW[row*TS + col*4]) = v;
    }

    // prologue: batch b_beg into buffer 0
    {
        const float* hb0 = g_h + (size_t)b_beg*ODIM;
        for (int idx = tid; idx < 16*TS/4; idx += 256) {
            int r = idx / (TS/4), col = idx % (TS/4);
            cp16(&sB[r*TS + col*4], &hb0[BOFF + r*SEQ + s0 + col*4]);
        }
        CP_COMMIT();
        for (int idx = tid; idx < TP*RNK; idx += 256) {
            int p = idx >> 4, r = idx & 15;
            sA[r*SA_ST + p] = hb0[p0*RNK + idx];
        }
        CP_WAIT0();
    }
    __syncthreads();

    for (int b = b_beg; b < b_end; ++b) {
        const int cur = (b - b_beg) & 1;
        const int nxt = cur ^ 1;
        const bool pf = (b + 1 < b_end);
        float apre[3];

        // issue prefetch for b+1 (cp.async B tile; A via LDG into regs)
        if (pf) {
            const float* hbn = g_h + (size_t)(b+1)*ODIM;
            for (int idx = tid; idx < 16*TS/4; idx += 256) {
                int r = idx / (TS/4), col = idx % (TS/4);
                cp16(&sB[nxt*SB_F + r*TS + col*4], &hbn[BOFF + r*SEQ + s0 + col*4]);
            }
            CP_COMMIT();
            #pragma unroll
            for (int k = 0; k < 3; ++k) {
                int idx = tid + k*256;
                apre[k] = (idx < TP*RNK) ? hbn[p0*RNK + idx] : 0.f;
            }
        }

        if (active) {
            const float* sBc = sB + cur*SB_F;
            const float* sAc = sA + cur*SA_F;

            unsigned long long acc[10][2];
            #pragma unroll
            for (int i = 0; i < 10; ++i) {
                ulonglong2 w = *reinterpret_cast<const ulonglong2*>(
                    &sW[(prow+i)*TS + scol]);
                acc[i][0] = w.x; acc[i][1] = w.y;
            }

            #pragma unroll
            for (int r = 0; r < RNK; ++r) {
                ulonglong2 bv = *reinterpret_cast<const ulonglong2*>(&sBc[r*TS + scol]);
                // 5 broadcast LDS.64 cover the 10 A values (8B-aligned)
                const float2* ap2 = reinterpret_cast<const float2*>(&sAc[r*SA_ST + prow]);
                float2 a01 = ap2[0], a23 = ap2[1], a45 = ap2[2];
                float2 a67 = ap2[3], a89 = ap2[4];
                unsigned long long d0 = dup2(a01.x), d1 = dup2(a01.y);
                unsigned long long d2 = dup2(a23.x), d3 = dup2(a23.y);
                unsigned long long d4 = dup2(a45.x), d5 = dup2(a45.y);
                unsigned long long d6 = dup2(a67.x), d7 = dup2(a67.y);
                unsigned long long d8 = dup2(a89.x), d9 = dup2(a89.y);
                acc[0][0] = ffma2(d0, bv.x, acc[0][0]);
                acc[0][1] = ffma2(d0, bv.y, acc[0][1]);
                acc[1][0] = ffma2(d1, bv.x, acc[1][0]);
                acc[1][1] = ffma2(d1, bv.y, acc[1][1]);
                acc[2][0] = ffma2(d2, bv.x, acc[2][0]);
                acc[2][1] = ffma2(d2, bv.y, acc[2][1]);
                acc[3][0] = ffma2(d3, bv.x, acc[3][0]);
                acc[3][1] = ffma2(d3, bv.y, acc[3][1]);
                acc[4][0] = ffma2(d4, bv.x, acc[4][0]);
                acc[4][1] = ffma2(d4, bv.y, acc[4][1]);
                acc[5][0] = ffma2(d5, bv.x, acc[5][0]);
                acc[5][1] = ffma2(d5, bv.y, acc[5][1]);
                acc[6][0] = ffma2(d6, bv.x, acc[6][0]);
                acc[6][1] = ffma2(d6, bv.y, acc[6][1]);
                acc[7][0] = ffma2(d7, bv.x, acc[7][0]);
                acc[7][1] = ffma2(d7, bv.y, acc[7][1]);
                acc[8][0] = ffma2(d8, bv.x, acc[8][0]);
                acc[8][1] = ffma2(d8, bv.y, acc[8][1]);
                acc[9][0] = ffma2(d9, bv.x, acc[9][0]);
                acc[9][1] = ffma2(d9, bv.y, acc[9][1]);
            }

            #pragma unroll
            for (int i = 0; i < 10; ++i) {
                size_t off = ((size_t)b*PRED + (p0 + prow + i))*SEQ + s0 + scol;
                __stcs(reinterpret_cast<float4*>(&weff[off]),
                       u2f4(acc[i][0], acc[i][1]));
            }
        }

        if (pf) {
            #pragma unroll
            for (int k = 0; k < 3; ++k) {
                int idx = tid + k*256;
                if (idx < TP*RNK) {
                    int p = idx >> 4, r = idx & 15;
                    sA[nxt*SA_F + r*SA_ST + p] = apre[k];
                }
            }
            CP_WAIT0();
        }
        __syncthreads();
    }
}

// ---------------- launch ----------------
extern "C" void kernel_launch(void* const* d_in, const int* in_sizes, int n_in,
                              void* d_out, int out_size) {
    const float* x   = (const float*)d_in[0];  // (256,720,1)
    const float* ctx = (const float*)d_in[1];  // (256,128)
    const float* W   = (const float*)d_in[2];  // (720,720)
    const float* W1  = (const float*)d_in[3];  // (64,128)
    const float* b1  = (const float*)d_in[4];  // (64,)
    const float* W2  = (const float*)d_in[5];  // (23040,64)
    const float* b2  = (const float*)d_in[6];  // (23040,)
    float* out  = (float*)d_out;
    float* y    = out;            // first YSZ elements
    float* weff = out + YSZ;      // then W_eff

    hidden_kernel<<<NB, 128>>>(ctx, W1, b1);
    mlp2_kernel<<<dim3(ODIM/64, NB/64), dim3(16,16)>>>(W2, b2);
    t_kernel<<<NB, 256>>>(x);
    yinit_kernel<<<YSZ/256, 256>>>(y);

    cudaFuncSetAttribute(ysplit_kernel, cudaFuncAttributeMaxDynamicSharedMemorySize, Y_SMEM);
    ysplit_kernel<<<dim3(PRED/YP, NB/YB, 4), dim3(64,4), Y_SMEM>>>(W, x, y);

    cudaFuncSetAttribute(weff_kernel, cudaFuncAttributeMaxDynamicSharedMemorySize, WEFF_SMEM);
    weff_kernel<<<dim3(PRED/TP, SEQ/TS, 8), dim3(64,4), WEFF_SMEM>>>(W, weff);
}

// round 13
// speedup vs baseline: 1.7915x; 1.0051x over previous
#include <cuda_runtime.h>
#include <cstdint>

// Problem constants
#define NB   256
#define SEQ  720
#define PRED 720
#define RNK  16
#define CTXD 128
#define HIDD 64
#define ODIM (RNK*(SEQ+PRED))   // 23040
#define BOFF (RNK*PRED)         // 11520, B_delta at h[b][11520 + r*720 + s]
#define YSZ  (NB*PRED)          // 184320

// Scratch (device globals: allocation-free)
__device__ __align__(128) float g_hidden[NB*HIDD];
__device__ __align__(128) float g_h[(size_t)NB*ODIM];   // hyper-MLP output, 23.6 MB
__device__ __align__(128) float g_t[NB*RNK];

// ---------------- packed f32x2 + async-copy helpers ----------------
__device__ __forceinline__ unsigned long long ffma2(unsigned long long a,
                                                    unsigned long long b,
                                                    unsigned long long c) {
    unsigned long long d;
    asm("fma.rn.f32x2 %0, %1, %2, %3;" : "=l"(d) : "l"(a), "l"(b), "l"(c));
    return d;
}
__device__ __forceinline__ unsigned long long dup2(float a) {
    unsigned long long d;
    asm("mov.b64 %0, {%1, %1};" : "=l"(d) : "f"(a));
    return d;
}
__device__ __forceinline__ float4 u2f4(unsigned long long a, unsigned long long b) {
    union { ulonglong2 u; float4 f; } c; c.u.x = a; c.u.y = b; return c.f;
}
__device__ __forceinline__ void unpack2(unsigned long long v, float& lo, float& hi) {
    asm("mov.b64 {%0, %1}, %2;" : "=f"(lo), "=f"(hi) : "l"(v));
}
__device__ __forceinline__ void cp16(void* smem_dst, const void* gmem_src) {
    unsigned s = (unsigned)__cvta_generic_to_shared(smem_dst);
    asm volatile("cp.async.cg.shared.global [%0], [%1], 16;" :: "r"(s), "l"(gmem_src));
}
#define CP_COMMIT() asm volatile("cp.async.commit_group;")
#define CP_WAIT0()  asm volatile("cp.async.wait_group 0;")

// ---------------- kernel 1a: hidden = relu(ctx @ W1^T + b1) ----------------
__global__ void hidden_kernel(const float* __restrict__ ctx,
                              const float* __restrict__ W1,
                              const float* __restrict__ b1) {
    __shared__ float sc[CTXD];
    int b = blockIdx.x;
    int t = threadIdx.x;               // 128 threads
    sc[t] = ctx[b*CTXD + t];
    __syncthreads();
    if (t < HIDD) {
        float s = b1[t];
        const float* w = W1 + t*CTXD;
        #pragma unroll 16
        for (int k = 0; k < CTXD; ++k) s += w[k]*sc[k];
        g_hidden[b*HIDD + t] = fmaxf(s, 0.f);
    }
}

// ---------------- kernel 1b: h = hidden @ W2^T + b2 ----------------
// 8-wide in o: each thread 4 batches x 8 outputs. Block tile 64b x 128o.
#define M2_SMEM ((64*132 + 64*68)*4)   // 51200 bytes
__global__ void __launch_bounds__(256) mlp2_kernel(const float* __restrict__ W2,
                                                   const float* __restrict__ b2) {
    extern __shared__ float m2s[];
    float* sW2T = m2s;              // [k][132] (128 o + pad)
    float* sHT  = m2s + 64*132;     // [k][68]
    const int tx = threadIdx.x, ty = threadIdx.y;   // (16,16)
    const int tid = ty*16 + tx;
    const int o0 = blockIdx.x*128, b0 = blockIdx.y*64;

    for (int idx = tid; idx < 128*64; idx += 256) {
        int i = idx >> 6, k = idx & 63;
        sW2T[k*132 + i] = W2[(size_t)(o0+i)*HIDD + k];
    }
    for (int idx = tid; idx < 64*64; idx += 256) {
        int i = idx >> 6, k = idx & 63;
        sHT[k*68 + i] = g_hidden[(b0+i)*HIDD + k];
    }
    __syncthreads();

    unsigned long long acc[4][4];
    #pragma unroll
    for (int j = 0; j < 4; ++j)
        #pragma unroll
        for (int q = 0; q < 4; ++q) acc[j][q] = 0ull;

    #pragma unroll 8
    for (int k = 0; k < 64; ++k) {
        float4 hb = *reinterpret_cast<const float4*>(&sHT[k*68 + tx*4]);
        ulonglong2 w0 = *reinterpret_cast<const ulonglong2*>(&sW2T[k*132 + ty*8]);
        ulonglong2 w1 = *reinterpret_cast<const ulonglong2*>(&sW2T[k*132 + ty*8 + 4]);
        const float hv[4] = {hb.x, hb.y, hb.z, hb.w};
        #pragma unroll
        for (int j = 0; j < 4; ++j) {
            unsigned long long ap = dup2(hv[j]);
            acc[j][0] = ffma2(ap, w0.x, acc[j][0]);
            acc[j][1] = ffma2(ap, w0.y, acc[j][1]);
            acc[j][2] = ffma2(ap, w1.x, acc[j][2]);
            acc[j][3] = ffma2(ap, w1.y, acc[j][3]);
        }
    }
    float4 bias0 = *reinterpret_cast<const float4*>(&b2[o0 + ty*8]);
    float4 bias1 = *reinterpret_cast<const float4*>(&b2[o0 + ty*8 + 4]);
    #pragma unroll
    for (int j = 0; j < 4; ++j) {
        float* dst = &g_h[(size_t)(b0 + tx*4 + j)*ODIM + o0 + ty*8];
        float4 v0 = u2f4(acc[j][0], acc[j][1]);
        float4 v1 = u2f4(acc[j][2], acc[j][3]);
        v0.x += bias0.x; v0.y += bias0.y; v0.z += bias0.z; v0.w += bias0.w;
        v1.x += bias1.x; v1.y += bias1.y; v1.z += bias1.z; v1.w += bias1.w;
        *reinterpret_cast<float4*>(dst)     = v0;
        *reinterpret_cast<float4*>(dst + 4) = v1;
    }
}

// ---------------- kernel 2: t[b][r] = B_delta[b,r,:] @ x[b,:] ----------------
__global__ void t_kernel(const float* __restrict__ x) {
    int b = blockIdx.x;
    int tid = threadIdx.x;            // 256 threads
    int r = tid >> 4, l = tid & 15;
    const float* bd = g_h + (size_t)b*ODIM + BOFF + r*SEQ;
    const float* xb = x + b*SEQ;
    float s = 0.f;
    for (int i = l; i < SEQ; i += 16) s += bd[i]*xb[i];
    #pragma unroll
    for (int off = 8; off; off >>= 1) s += __shfl_down_sync(0xffffffffu, s, off, 16);
    if (l == 0) g_t[b*RNK + r] = s;
}

// ---------------- kernel 3a: y init = A[b,p,:]·t[b,:] (coalesced) -----------
#define YI_SMEM (720*17*4 + 64)   // sA padded [720][17] + t
__global__ void yinit_kernel(float* __restrict__ y) {
    extern __shared__ float ysm0[];
    float* sA = ysm0;                 // [720][17]
    float* st = ysm0 + 720*17;        // [16]
    const int b = blockIdx.x, tid = threadIdx.x;   // 256 threads
    // fully-coalesced A slab load: 720*16 floats = 2880 float4
    const float4* src = reinterpret_cast<const float4*>(g_h + (size_t)b*ODIM);
    for (int i = tid; i < 2880; i += 256) {
        float4 v = src[i];
        int p = i >> 2, rq = (i & 3)*4;
        float* d = &sA[p*17 + rq];
        d[0] = v.x; d[1] = v.y; d[2] = v.z; d[3] = v.w;
    }
    if (tid < RNK) st[tid] = g_t[b*RNK + tid];
    __syncthreads();
    for (int p = tid; p < PRED; p += 256) {
        const float* a = &sA[p*17];
        float s = 0.f;
        #pragma unroll
        for (int r = 0; r < RNK; ++r) s += a[r]*st[r];
        y[(size_t)b*PRED + p] = s;
    }
}

// ---------------- kernel 3b: y += W@x, split-K with atomics ------------------
#define YP  16
#define YB  64
#define YKP 90            // k-pairs per chunk (180 k)
#define YXST 65           // sX2 row stride in float2
#define Y_SMEM (YKP*YXST*8 + YP*YKP*8)    // 58320 bytes

__global__ void __launch_bounds__(256) ysplit_kernel(const float* __restrict__ W,
                                                     const float* __restrict__ x,
                                                     float* __restrict__ y) {
    extern __shared__ float ysm[];
    float2* sX2 = reinterpret_cast<float2*>(ysm);            // [kk][b] padded
    float2* sW2 = sX2 + YKP*YXST;                            // [p][kk]

    const int tx = threadIdx.x, ty = threadIdx.y;            // (64,4)
    const int tid = ty*64 + tx;
    const int p0 = blockIdx.x*YP, b0 = blockIdx.y*YB;
    const int k0 = blockIdx.z*YKP*2;

    for (int idx = tid; idx < YB*YKP; idx += 256) {
        int b = idx / YKP, kk = idx - (idx/YKP)*YKP;
        sX2[kk*YXST + b] =
            *reinterpret_cast<const float2*>(&x[(size_t)(b0+b)*SEQ + k0 + kk*2]);
    }
    for (int idx = tid; idx < YP*YKP; idx += 256) {
        int p = idx / YKP, kk = idx - (idx/YKP)*YKP;
        sW2[p*YKP + kk] =
            *reinterpret_cast<const float2*>(&W[(size_t)(p0+p)*SEQ + k0 + kk*2]);
    }
    __syncthreads();

    unsigned long long acc[4] = {0ull, 0ull, 0ull, 0ull};
    #pragma unroll 10
    for (int kk = 0; kk < YKP; ++kk) {
        unsigned long long xv =
            *reinterpret_cast<const unsigned long long*>(&sX2[kk*YXST + tx]);
        #pragma unroll
        for (int i = 0; i < 4; ++i) {
            unsigned long long wv =
                *reinterpret_cast<const unsigned long long*>(&sW2[(ty*4+i)*YKP + kk]);
            acc[i] = ffma2(wv, xv, acc[i]);
        }
    }
    const int b = b0 + tx;
    #pragma unroll
    for (int i = 0; i < 4; ++i) {
        float lo, hi; unpack2(acc[i], lo, hi);
        atomicAdd(&y[(size_t)b*PRED + p0 + ty*4 + i], lo + hi);
    }
}

// ---------------- kernel 4: W_eff = W + A_delta @ B_delta --------------------
// R12 config (TP=40, 3 blk/SM, double-buffered), store-policy experiment:
// plain STG instead of __stcs (A/B test against the flat ~175us baseline).
#define TP 40
#define TS 240
#define SB_F (16*TS)                       // 3840 floats per B buffer
#define SA_ST 44                           // A row stride in floats (40 + pad)
#define SA_F (RNK*SA_ST)                   // 704 floats per A buffer
#define BCH 32                             // batches per block (z=8)
#define WEFF_SMEM ((TP*TS + 2*SB_F + 2*SA_F)*4)   // 74752 bytes

__global__ void __launch_bounds__(256, 3) weff_kernel(const float* __restrict__ W,
                                                      float* __restrict__ weff) {
    extern __shared__ float smem[];
    float* sW = smem;                                 // [TP][TS]
    float* sB = smem + TP*TS;                         // [2][16][TS]
    float* sA = smem + TP*TS + 2*SB_F;                // [2][16][SA_ST] plain

    const int tx = threadIdx.x, ty = threadIdx.y;     // blockDim (64,4)
    const int tid = ty*64 + tx;
    const int p0 = blockIdx.x * TP;
    const int s0 = blockIdx.y * TS;
    const int b_beg = blockIdx.z * BCH;
    const int b_end = min(NB, b_beg + BCH);
    const bool active = (tx < TS/4);
    const int scol = tx*4;
    const int prow = ty*10;                           // 10 contiguous rows, even

    // W tile -> SMEM, once per block
    for (int idx = tid; idx < TP*TS/4; idx += 256) {
        int row = idx / (TS/4), col = idx % (TS/4);
        float4 v = *reinterpret_cast<const float4*>(&W[(size_t)(p0+row)*SEQ + s0 + col*4]);
        *reinterpret_cast<float4*>(&sW[row*TS + col*4]) = v;
    }

    // prologue: batch b_beg into buffer 0
    {
        const float* hb0 = g_h + (size_t)b_beg*ODIM;
        for (int idx = tid; idx < 16*TS/4; idx += 256) {
            int r = idx / (TS/4), col = idx % (TS/4);
            cp16(&sB[r*TS + col*4], &hb0[BOFF + r*SEQ + s0 + col*4]);
        }
        CP_COMMIT();
        for (int idx = tid; idx < TP*RNK; idx += 256) {
            int p = idx >> 4, r = idx & 15;
            sA[r*SA_ST + p] = hb0[p0*RNK + idx];
        }
        CP_WAIT0();
    }
    __syncthreads();

    for (int b = b_beg; b < b_end; ++b) {
        const int cur = (b - b_beg) & 1;
        const int nxt = cur ^ 1;
        const bool pf = (b + 1 < b_end);
        float apre[3];

        // issue prefetch for b+1 (cp.async B tile; A via LDG into regs)
        if (pf) {
            const float* hbn = g_h + (size_t)(b+1)*ODIM;
            for (int idx = tid; idx < 16*TS/4; idx += 256) {
                int r = idx / (TS/4), col = idx % (TS/4);
                cp16(&sB[nxt*SB_F + r*TS + col*4], &hbn[BOFF + r*SEQ + s0 + col*4]);
            }
            CP_COMMIT();
            #pragma unroll
            for (int k = 0; k < 3; ++k) {
                int idx = tid + k*256;
                apre[k] = (idx < TP*RNK) ? hbn[p0*RNK + idx] : 0.f;
            }
        }

        if (active) {
            const float* sBc = sB + cur*SB_F;
            const float* sAc = sA + cur*SA_F;

            unsigned long long acc[10][2];
            #pragma unroll
            for (int i = 0; i < 10; ++i) {
                ulonglong2 w = *reinterpret_cast<const ulonglong2*>(
                    &sW[(prow+i)*TS + scol]);
                acc[i][0] = w.x; acc[i][1] = w.y;
            }

            #pragma unroll
            for (int r = 0; r < RNK; ++r) {
                ulonglong2 bv = *reinterpret_cast<const ulonglong2*>(&sBc[r*TS + scol]);
                const float2* ap2 = reinterpret_cast<const float2*>(&sAc[r*SA_ST + prow]);
                float2 a01 = ap2[0], a23 = ap2[1], a45 = ap2[2];
                float2 a67 = ap2[3], a89 = ap2[4];
                unsigned long long d0 = dup2(a01.x), d1 = dup2(a01.y);
                unsigned long long d2 = dup2(a23.x), d3 = dup2(a23.y);
                unsigned long long d4 = dup2(a45.x), d5 = dup2(a45.y);
                unsigned long long d6 = dup2(a67.x), d7 = dup2(a67.y);
                unsigned long long d8 = dup2(a89.x), d9 = dup2(a89.y);
                acc[0][0] = ffma2(d0, bv.x, acc[0][0]);
                acc[0][1] = ffma2(d0, bv.y, acc[0][1]);
                acc[1][0] = ffma2(d1, bv.x, acc[1][0]);
                acc[1][1] = ffma2(d1, bv.y, acc[1][1]);
                acc[2][0] = ffma2(d2, bv.x, acc[2][0]);
                acc[2][1] = ffma2(d2, bv.y, acc[2][1]);
                acc[3][0] = ffma2(d3, bv.x, acc[3][0]);
                acc[3][1] = ffma2(d3, bv.y, acc[3][1]);
                acc[4][0] = ffma2(d4, bv.x, acc[4][0]);
                acc[4][1] = ffma2(d4, bv.y, acc[4][1]);
                acc[5][0] = ffma2(d5, bv.x, acc[5][0]);
                acc[5][1] = ffma2(d5, bv.y, acc[5][1]);
                acc[6][0] = ffma2(d6, bv.x, acc[6][0]);
                acc[6][1] = ffma2(d6, bv.y, acc[6][1]);
                acc[7][0] = ffma2(d7, bv.x, acc[7][0]);
                acc[7][1] = ffma2(d7, bv.y, acc[7][1]);
                acc[8][0] = ffma2(d8, bv.x, acc[8][0]);
                acc[8][1] = ffma2(d8, bv.y, acc[8][1]);
                acc[9][0] = ffma2(d9, bv.x, acc[9][0]);
                acc[9][1] = ffma2(d9, bv.y, acc[9][1]);
            }

            #pragma unroll
            for (int i = 0; i < 10; ++i) {
                size_t off = ((size_t)b*PRED + (p0 + prow + i))*SEQ + s0 + scol;
                *reinterpret_cast<float4*>(&weff[off]) = u2f4(acc[i][0], acc[i][1]);
            }
        }

        if (pf) {
            #pragma unroll
            for (int k = 0; k < 3; ++k) {
                int idx = tid + k*256;
                if (idx < TP*RNK) {
                    int p = idx >> 4, r = idx & 15;
                    sA[nxt*SA_F + r*SA_ST + p] = apre[k];
                }
            }
            CP_WAIT0();
        }
        __syncthreads();
    }
}

// ---------------- launch ----------------
extern "C" void kernel_launch(void* const* d_in, const int* in_sizes, int n_in,
                              void* d_out, int out_size) {
    const float* x   = (const float*)d_in[0];  // (256,720,1)
    const float* ctx = (const float*)d_in[1];  // (256,128)
    const float* W   = (const float*)d_in[2];  // (720,720)
    const float* W1  = (const float*)d_in[3];  // (64,128)
    const float* b1  = (const float*)d_in[4];  // (64,)
    const float* W2  = (const float*)d_in[5];  // (23040,64)
    const float* b2  = (const float*)d_in[6];  // (23040,)
    float* out  = (float*)d_out;
    float* y    = out;            // first YSZ elements
    float* weff = out + YSZ;      // then W_eff

    hidden_kernel<<<NB, 128>>>(ctx, W1, b1);

    cudaFuncSetAttribute(mlp2_kernel, cudaFuncAttributeMaxDynamicSharedMemorySize, M2_SMEM);
    mlp2_kernel<<<dim3(ODIM/128, NB/64), dim3(16,16), M2_SMEM>>>(W2, b2);

    t_kernel<<<NB, 256>>>(x);

    cudaFuncSetAttribute(yinit_kernel, cudaFuncAttributeMaxDynamicSharedMemorySize, YI_SMEM);
    yinit_kernel<<<NB, 256, YI_SMEM>>>(y);

    cudaFuncSetAttribute(ysplit_kernel, cudaFuncAttributeMaxDynamicSharedMemorySize, Y_SMEM);
    ysplit_kernel<<<dim3(PRED/YP, NB/YB, 4), dim3(64,4), Y_SMEM>>>(W, x, y);

    cudaFuncSetAttribute(weff_kernel, cudaFuncAttributeMaxDynamicSharedMemorySize, WEFF_SMEM);
    weff_kernel<<<dim3(PRED/TP, SEQ/TS, 8), dim3(64,4), WEFF_SMEM>>>(W, weff);
}